// round 1
// baseline (speedup 1.0000x reference)
#include <cuda_runtime.h>
#include <math.h>

#define N_NODES 50000
#define N_EDGES 800000
#define H       96
#define IN_DIM  256
#define F       288   // per-node feature row: [ h(96) | g_d(96) | g_s(96) ]

// Scratch (device globals — no allocation allowed in kernel_launch)
__device__ float g_feat[(size_t)N_NODES * F];   // 57.6 MB
__device__ float g_WcT[IN_DIM * F];             // combined weight, transposed [256,288]
__device__ float g_bc[F];
__device__ float g_zacc[2 * N_NODES];

// ---------------------------------------------------------------------------
// Kernel 1: build combined weight WcT[k][r] and bias bc[r]; zero zacc.
//   rows 0..95   : W_in                      bias b_in
//   rows 96..191 : W_gd @ W_in               bias W_gd @ b_in
//   rows 192..287: W_gs @ W_in               bias W_gs @ b_in + b_gate
// (W_gd = W_gate[:, :96], W_gs = W_gate[:, 96:192]; W_gate row-major [96,192])
// ---------------------------------------------------------------------------
__global__ void prep_kernel(const float* __restrict__ W_in, const float* __restrict__ b_in,
                            const float* __restrict__ W_gate, const float* __restrict__ b_gate) {
    int r = blockIdx.x;      // 0..287
    int k = threadIdx.x;     // 0..255
    float v;
    if (r < H) {
        v = W_in[r * IN_DIM + k];
    } else if (r < 2 * H) {
        int i = r - H;
        float acc = 0.f;
        #pragma unroll 4
        for (int j = 0; j < H; ++j) acc = fmaf(W_gate[i * (2 * H) + j], W_in[j * IN_DIM + k], acc);
        v = acc;
    } else {
        int i = r - 2 * H;
        float acc = 0.f;
        #pragma unroll 4
        for (int j = 0; j < H; ++j) acc = fmaf(W_gate[i * (2 * H) + H + j], W_in[j * IN_DIM + k], acc);
        v = acc;
    }
    g_WcT[k * F + r] = v;

    if (k == 0) {
        float b;
        if (r < H) {
            b = b_in[r];
        } else if (r < 2 * H) {
            int i = r - H;
            float acc = 0.f;
            for (int j = 0; j < H; ++j) acc = fmaf(W_gate[i * (2 * H) + j], b_in[j], acc);
            b = acc;
        } else {
            int i = r - 2 * H;
            float acc = 0.f;
            for (int j = 0; j < H; ++j) acc = fmaf(W_gate[i * (2 * H) + H + j], b_in[j], acc);
            b = acc + b_gate[i];
        }
        g_bc[r] = b;
    }

    // zero the logit accumulator (grid-stride; 288*256 threads cover 100000)
    for (int idx = blockIdx.x * blockDim.x + threadIdx.x; idx < 2 * N_NODES;
         idx += gridDim.x * blockDim.x)
        g_zacc[idx] = 0.f;
}

// ---------------------------------------------------------------------------
// Kernel 2: feat[N,288] = x[N,256] @ WcT + bc    (classic tiled fp32 GEMM)
// ---------------------------------------------------------------------------
#define BM 64
#define BN 64
#define BK 32

__global__ __launch_bounds__(256) void gemm_kernel(const float* __restrict__ x) {
    __shared__ float As[BK][BM];
    __shared__ float Bs[BK][BN];
    int tid = threadIdx.x;
    int row0 = blockIdx.x * BM;
    int col0 = blockIdx.y * BN;
    int ty = tid / 16;   // 0..15 -> rows ty*4 .. ty*4+3
    int tx = tid % 16;   // 0..15 -> cols tx*4 .. tx*4+3
    float acc[4][4] = {};

    for (int k0 = 0; k0 < IN_DIM; k0 += BK) {
        // ---- load A tile (64 rows x 32 k), 8 floats per thread, vectorized
        {
            int r  = tid / 4;            // 0..63
            int kk = (tid % 4) * 8;      // 0,8,16,24
            int grow = row0 + r;
            if (grow < N_NODES) {
                const float4* p = reinterpret_cast<const float4*>(
                    x + (size_t)grow * IN_DIM + k0 + kk);
                float4 v0 = p[0], v1 = p[1];
                As[kk + 0][r] = v0.x; As[kk + 1][r] = v0.y;
                As[kk + 2][r] = v0.z; As[kk + 3][r] = v0.w;
                As[kk + 4][r] = v1.x; As[kk + 5][r] = v1.y;
                As[kk + 6][r] = v1.z; As[kk + 7][r] = v1.w;
            } else {
                #pragma unroll
                for (int q = 0; q < 8; ++q) As[kk + q][r] = 0.f;
            }
        }
        // ---- load B tile: Bs[kk][c] = WcT[(k0+kk)*F + col0+c]
        {
            int kk = tid / 8;            // 0..31
            int c  = (tid % 8) * 8;      // 0..56
            #pragma unroll
            for (int q = 0; q < 8; ++q) {
                int gc = col0 + c + q;
                Bs[kk][c + q] = (gc < F) ? g_WcT[(size_t)(k0 + kk) * F + gc] : 0.f;
            }
        }
        __syncthreads();

        #pragma unroll
        for (int kk = 0; kk < BK; ++kk) {
            float ra[4], rb[4];
            #pragma unroll
            for (int i = 0; i < 4; ++i) ra[i] = As[kk][ty * 4 + i];
            #pragma unroll
            for (int j = 0; j < 4; ++j) rb[j] = Bs[kk][tx * 4 + j];
            #pragma unroll
            for (int i = 0; i < 4; ++i)
                #pragma unroll
                for (int j = 0; j < 4; ++j)
                    acc[i][j] = fmaf(ra[i], rb[j], acc[i][j]);
        }
        __syncthreads();
    }

    #pragma unroll
    for (int i = 0; i < 4; ++i) {
        int grow = row0 + ty * 4 + i;
        if (grow >= N_NODES) continue;
        #pragma unroll
        for (int j = 0; j < 4; ++j) {
            int gc = col0 + tx * 4 + j;
            if (gc < F)
                g_feat[(size_t)grow * F + gc] = acc[i][j] + g_bc[gc];
        }
    }
}

// ---------------------------------------------------------------------------
// Kernel 3: per-edge. One warp per edge (3 elements/lane).
//   a[e]   = tanh((g_d[dst] + g_s[src]) / sqrt(192))        -> d_out
//   msg    = h[src] * a * d[src]*d[dst]
//   zacc[dst][c] += W_clf[c] . msg     (warp-reduced, 2 atomics/edge)
// ---------------------------------------------------------------------------
__global__ __launch_bounds__(256) void edge_kernel(const int* __restrict__ src,
                                                   const int* __restrict__ dst,
                                                   const float* __restrict__ dvec,
                                                   const float* __restrict__ Wclf,
                                                   float* __restrict__ a_out) {
    const float inv = rsqrtf(2.0f * H);   // 1/sqrt(192)
    int lane = threadIdx.x & 31;
    int warp = (blockIdx.x * blockDim.x + threadIdx.x) >> 5;
    int nwarps = (gridDim.x * blockDim.x) >> 5;

    float c0[3], c1[3];
    #pragma unroll
    for (int k = 0; k < 3; ++k) {
        c0[k] = Wclf[k * 32 + lane];
        c1[k] = Wclf[H + k * 32 + lane];
    }

    for (int e = warp; e < N_EDGES; e += nwarps) {
        int s = src[e], t = dst[e];
        float ed = dvec[s] * dvec[t];
        const float* fs = g_feat + (size_t)s * F;
        const float* ft = g_feat + (size_t)t * F;
        float s0 = 0.f, s1 = 0.f;
        #pragma unroll
        for (int k = 0; k < 3; ++k) {
            int idx = k * 32 + lane;
            float gd = ft[H + idx];          // g_d[dst]
            float gs = fs[2 * H + idx];      // g_s[src] (bias already folded in)
            float hs = fs[idx];              // h[src]
            float aa = tanhf((gd + gs) * inv);
            a_out[(size_t)e * H + idx] = aa;
            float m = hs * aa * ed;
            s0 = fmaf(c0[k], m, s0);
            s1 = fmaf(c1[k], m, s1);
        }
        #pragma unroll
        for (int off = 16; off > 0; off >>= 1) {
            s0 += __shfl_down_sync(0xffffffffu, s0, off);
            s1 += __shfl_down_sync(0xffffffffu, s1, off);
        }
        if (lane == 0) {
            atomicAdd(&g_zacc[2 * t + 0], s0);
            atomicAdd(&g_zacc[2 * t + 1], s1);
        }
    }
}

// ---------------------------------------------------------------------------
// Kernel 4: z = log_softmax(zacc + b_clf) over the 2 classes.
// ---------------------------------------------------------------------------
__global__ void final_kernel(const float* __restrict__ b_clf, float* __restrict__ z_out) {
    int n = blockIdx.x * blockDim.x + threadIdx.x;
    if (n >= N_NODES) return;
    float l0 = g_zacc[2 * n + 0] + b_clf[0];
    float l1 = g_zacc[2 * n + 1] + b_clf[1];
    float m = fmaxf(l0, l1);
    float lse = m + logf(expf(l0 - m) + expf(l1 - m));
    z_out[2 * n + 0] = l0 - lse;
    z_out[2 * n + 1] = l1 - lse;
}

// ---------------------------------------------------------------------------
extern "C" void kernel_launch(void* const* d_in, const int* in_sizes, int n_in,
                              void* d_out, int out_size) {
    const float* x      = (const float*)d_in[0];
    const float* dvec   = (const float*)d_in[1];
    const int*   src    = (const int*)  d_in[2];
    const int*   dst    = (const int*)  d_in[3];
    const float* W_in   = (const float*)d_in[4];
    const float* b_in   = (const float*)d_in[5];
    const float* W_gate = (const float*)d_in[6];
    const float* b_gate = (const float*)d_in[7];
    const float* W_clf  = (const float*)d_in[8];
    const float* b_clf  = (const float*)d_in[9];

    float* out   = (float*)d_out;
    float* z_out = out;                 // [N, 2]
    float* a_out = out + 2 * N_NODES;   // [E, 96]

    prep_kernel<<<F, 256>>>(W_in, b_in, W_gate, b_gate);

    dim3 ggrid((N_NODES + BM - 1) / BM, (F + BN - 1) / BN);
    gemm_kernel<<<ggrid, 256>>>(x);

    edge_kernel<<<4096, 256>>>(src, dst, dvec, W_clf, a_out);

    final_kernel<<<(N_NODES + 255) / 256, 256>>>(b_clf, z_out);
}

// round 2
// speedup vs baseline: 1.8824x; 1.8824x over previous
#include <cuda_runtime.h>
#include <math.h>

#define N_NODES 50000
#define N_EDGES 800000
#define H       96
#define IN_DIM  256
#define F       288   // per-node feature row: [ h(96) | g_d(96) | g_s(96) ]

// Scratch (device globals — no allocation allowed in kernel_launch)
__device__ float g_feat[(size_t)N_NODES * F];   // 57.6 MB
__device__ float g_WcT[IN_DIM * F];             // combined weight, transposed [256,288]
__device__ float g_bc[F];
__device__ float g_zacc[2 * N_NODES];

// ---------------------------------------------------------------------------
// Kernel 1: build combined weight WcT[k][r] and bias bc[r]; zero zacc.
// ---------------------------------------------------------------------------
__global__ void prep_kernel(const float* __restrict__ W_in, const float* __restrict__ b_in,
                            const float* __restrict__ W_gate, const float* __restrict__ b_gate) {
    int r = blockIdx.x;      // 0..287
    int k = threadIdx.x;     // 0..255
    float v;
    if (r < H) {
        v = W_in[r * IN_DIM + k];
    } else if (r < 2 * H) {
        int i = r - H;
        float acc = 0.f;
        #pragma unroll 4
        for (int j = 0; j < H; ++j) acc = fmaf(W_gate[i * (2 * H) + j], W_in[j * IN_DIM + k], acc);
        v = acc;
    } else {
        int i = r - 2 * H;
        float acc = 0.f;
        #pragma unroll 4
        for (int j = 0; j < H; ++j) acc = fmaf(W_gate[i * (2 * H) + H + j], W_in[j * IN_DIM + k], acc);
        v = acc;
    }
    g_WcT[k * F + r] = v;

    if (k == 0) {
        float b;
        if (r < H) {
            b = b_in[r];
        } else if (r < 2 * H) {
            int i = r - H;
            float acc = 0.f;
            for (int j = 0; j < H; ++j) acc = fmaf(W_gate[i * (2 * H) + j], b_in[j], acc);
            b = acc;
        } else {
            int i = r - 2 * H;
            float acc = 0.f;
            for (int j = 0; j < H; ++j) acc = fmaf(W_gate[i * (2 * H) + H + j], b_in[j], acc);
            b = acc + b_gate[i];
        }
        g_bc[r] = b;
    }

    for (int idx = blockIdx.x * blockDim.x + threadIdx.x; idx < 2 * N_NODES;
         idx += gridDim.x * blockDim.x)
        g_zacc[idx] = 0.f;
}

// ---------------------------------------------------------------------------
// Kernel 2: feat[N,288] = x[N,256] @ WcT + bc  via mma.sync tf32 tensor cores
//   Block tile 128x96x(K=32), 8 warps (4x2), warp tile 32x48, mma m16n8k8.
// ---------------------------------------------------------------------------
#define BM 128
#define BN 96
#define BK 32
#define AS_LD 36    // bank = (4*row + k) % 32 -> conflict-free frag loads
#define BS_LD 104   // bank = (8*k + n) % 32  -> conflict-free frag loads

__device__ __forceinline__ unsigned f2tf32(float f) {
    unsigned u;
    asm("cvt.rna.tf32.f32 %0, %1;" : "=r"(u) : "f"(f));
    return u;
}

__global__ __launch_bounds__(256) void gemm_tc_kernel(const float* __restrict__ x) {
    __shared__ float As[BM][AS_LD];
    __shared__ float Bs[BK][BS_LD];

    const int tid  = threadIdx.x;
    const int warp = tid >> 5;
    const int lane = tid & 31;
    const int gid  = lane >> 2;   // groupID 0..7
    const int tig  = lane & 3;    // thread-in-group 0..3

    const int row0 = blockIdx.x * BM;
    const int col0 = blockIdx.y * BN;
    const int wm = warp >> 1;           // 0..3
    const int wn = warp & 1;            // 0..1
    const int m_warp = wm * 32;
    const int n_warp = wn * 48;

    float c[2][6][4];
    #pragma unroll
    for (int i = 0; i < 2; ++i)
        #pragma unroll
        for (int j = 0; j < 6; ++j)
            #pragma unroll
            for (int q = 0; q < 4; ++q) c[i][j][q] = 0.f;

    // global-load assignments
    const int ar = tid >> 3;            // 0..31 (row group, +32 per pass)
    const int ac = (tid & 7) * 4;       // k offset 0..28
    const int bk = tid >> 3;            // 0..31
    const int bc = (tid & 7) * 12;      // 0..84

    for (int k0 = 0; k0 < IN_DIM; k0 += BK) {
        // load A tile: 128 x 32 floats
        #pragma unroll
        for (int p = 0; p < 4; ++p) {
            int r = ar + p * 32;
            int grow = row0 + r;
            float4 v;
            if (grow < N_NODES)
                v = *reinterpret_cast<const float4*>(x + (size_t)grow * IN_DIM + k0 + ac);
            else
                v = make_float4(0.f, 0.f, 0.f, 0.f);
            As[r][ac + 0] = v.x; As[r][ac + 1] = v.y;
            As[r][ac + 2] = v.z; As[r][ac + 3] = v.w;
        }
        // load B tile: 32 x 96 floats (F=288 divisible by 4, col0 multiple of 96)
        {
            const float* bp = g_WcT + (size_t)(k0 + bk) * F + col0 + bc;
            float4 v0 = *reinterpret_cast<const float4*>(bp + 0);
            float4 v1 = *reinterpret_cast<const float4*>(bp + 4);
            float4 v2 = *reinterpret_cast<const float4*>(bp + 8);
            Bs[bk][bc + 0] = v0.x; Bs[bk][bc + 1] = v0.y; Bs[bk][bc + 2]  = v0.z; Bs[bk][bc + 3]  = v0.w;
            Bs[bk][bc + 4] = v1.x; Bs[bk][bc + 5] = v1.y; Bs[bk][bc + 6]  = v1.z; Bs[bk][bc + 7]  = v1.w;
            Bs[bk][bc + 8] = v2.x; Bs[bk][bc + 9] = v2.y; Bs[bk][bc + 10] = v2.z; Bs[bk][bc + 11] = v2.w;
        }
        __syncthreads();

        #pragma unroll
        for (int ks = 0; ks < 4; ++ks) {
            const int kk = ks * 8;
            unsigned a[2][4], b[6][2];
            #pragma unroll
            for (int mt = 0; mt < 2; ++mt) {
                int rA = m_warp + mt * 16 + gid;
                a[mt][0] = f2tf32(As[rA    ][kk + tig    ]);
                a[mt][1] = f2tf32(As[rA + 8][kk + tig    ]);
                a[mt][2] = f2tf32(As[rA    ][kk + tig + 4]);
                a[mt][3] = f2tf32(As[rA + 8][kk + tig + 4]);
            }
            #pragma unroll
            for (int nt = 0; nt < 6; ++nt) {
                int cB = n_warp + nt * 8 + gid;
                b[nt][0] = f2tf32(Bs[kk + tig    ][cB]);
                b[nt][1] = f2tf32(Bs[kk + tig + 4][cB]);
            }
            #pragma unroll
            for (int mt = 0; mt < 2; ++mt)
                #pragma unroll
                for (int nt = 0; nt < 6; ++nt) {
                    asm volatile(
                        "mma.sync.aligned.m16n8k8.row.col.f32.tf32.tf32.f32 "
                        "{%0,%1,%2,%3}, {%4,%5,%6,%7}, {%8,%9}, {%0,%1,%2,%3};\n"
                        : "+f"(c[mt][nt][0]), "+f"(c[mt][nt][1]),
                          "+f"(c[mt][nt][2]), "+f"(c[mt][nt][3])
                        : "r"(a[mt][0]), "r"(a[mt][1]), "r"(a[mt][2]), "r"(a[mt][3]),
                          "r"(b[nt][0]), "r"(b[nt][1]));
                }
        }
        __syncthreads();
    }

    // store with bias
    #pragma unroll
    for (int mt = 0; mt < 2; ++mt) {
        #pragma unroll
        for (int half = 0; half < 2; ++half) {
            int grow = row0 + m_warp + mt * 16 + gid + half * 8;
            if (grow >= N_NODES) continue;
            float* outp = g_feat + (size_t)grow * F;
            #pragma unroll
            for (int nt = 0; nt < 6; ++nt) {
                int gc = col0 + n_warp + nt * 8 + 2 * tig;
                float v0 = c[mt][nt][half * 2 + 0] + g_bc[gc];
                float v1 = c[mt][nt][half * 2 + 1] + g_bc[gc + 1];
                outp[gc]     = v0;
                outp[gc + 1] = v1;
            }
        }
    }
}

// ---------------------------------------------------------------------------
// Kernel 3: per-edge. One warp per edge (3 elements/lane).
// ---------------------------------------------------------------------------
__device__ __forceinline__ float fast_tanh(float v) {
    float r;
    asm("tanh.approx.f32 %0, %1;" : "=f"(r) : "f"(v));
    return r;
}

__global__ __launch_bounds__(256) void edge_kernel(const int* __restrict__ src,
                                                   const int* __restrict__ dst,
                                                   const float* __restrict__ dvec,
                                                   const float* __restrict__ Wclf,
                                                   float* __restrict__ a_out) {
    const float inv = rsqrtf(2.0f * H);   // 1/sqrt(192)
    int lane = threadIdx.x & 31;
    int warp = (blockIdx.x * blockDim.x + threadIdx.x) >> 5;
    int nwarps = (gridDim.x * blockDim.x) >> 5;

    float c0[3], c1[3];
    #pragma unroll
    for (int k = 0; k < 3; ++k) {
        c0[k] = Wclf[k * 32 + lane];
        c1[k] = Wclf[H + k * 32 + lane];
    }

    for (int e = warp; e < N_EDGES; e += nwarps) {
        int s = src[e], t = dst[e];
        float ed = dvec[s] * dvec[t];
        const float* fs = g_feat + (size_t)s * F;
        const float* ft = g_feat + (size_t)t * F;
        float s0 = 0.f, s1 = 0.f;
        #pragma unroll
        for (int k = 0; k < 3; ++k) {
            int idx = k * 32 + lane;
            float gd = ft[H + idx];          // g_d[dst]
            float gs = fs[2 * H + idx];      // g_s[src]
            float hs = fs[idx];              // h[src]
            float aa = fast_tanh((gd + gs) * inv);
            a_out[(size_t)e * H + idx] = aa;
            float m = hs * aa * ed;
            s0 = fmaf(c0[k], m, s0);
            s1 = fmaf(c1[k], m, s1);
        }
        #pragma unroll
        for (int off = 16; off > 0; off >>= 1) {
            s0 += __shfl_down_sync(0xffffffffu, s0, off);
            s1 += __shfl_down_sync(0xffffffffu, s1, off);
        }
        if (lane == 0) {
            atomicAdd(&g_zacc[2 * t + 0], s0);
            atomicAdd(&g_zacc[2 * t + 1], s1);
        }
    }
}

// ---------------------------------------------------------------------------
// Kernel 4: z = log_softmax(zacc + b_clf) over the 2 classes.
// ---------------------------------------------------------------------------
__global__ void final_kernel(const float* __restrict__ b_clf, float* __restrict__ z_out) {
    int n = blockIdx.x * blockDim.x + threadIdx.x;
    if (n >= N_NODES) return;
    float l0 = g_zacc[2 * n + 0] + b_clf[0];
    float l1 = g_zacc[2 * n + 1] + b_clf[1];
    float m = fmaxf(l0, l1);
    float lse = m + logf(expf(l0 - m) + expf(l1 - m));
    z_out[2 * n + 0] = l0 - lse;
    z_out[2 * n + 1] = l1 - lse;
}

// ---------------------------------------------------------------------------
extern "C" void kernel_launch(void* const* d_in, const int* in_sizes, int n_in,
                              void* d_out, int out_size) {
    const float* x      = (const float*)d_in[0];
    const float* dvec   = (const float*)d_in[1];
    const int*   src    = (const int*)  d_in[2];
    const int*   dst    = (const int*)  d_in[3];
    const float* W_in   = (const float*)d_in[4];
    const float* b_in   = (const float*)d_in[5];
    const float* W_gate = (const float*)d_in[6];
    const float* b_gate = (const float*)d_in[7];
    const float* W_clf  = (const float*)d_in[8];
    const float* b_clf  = (const float*)d_in[9];

    float* out   = (float*)d_out;
    float* z_out = out;                 // [N, 2]
    float* a_out = out + 2 * N_NODES;   // [E, 96]

    prep_kernel<<<F, 256>>>(W_in, b_in, W_gate, b_gate);

    dim3 ggrid((N_NODES + BM - 1) / BM, F / BN);
    gemm_tc_kernel<<<ggrid, 256>>>(x);

    edge_kernel<<<4096, 256>>>(src, dst, dvec, W_clf, a_out);

    final_kernel<<<(N_NODES + 255) / 256, 256>>>(b_clf, z_out);
}

// round 3
// speedup vs baseline: 2.2928x; 1.2181x over previous
#include <cuda_runtime.h>
#include <cuda_fp16.h>
#include <math.h>

#define N_NODES 50000
#define N_EDGES 800000
#define H       96
#define IN_DIM  256
#define F       288   // combined output: [ h(96) | g_d(96) | g_s(96) ]

// Scratch (device globals — no allocation in kernel_launch)
__device__ __half g_hs[(size_t)N_NODES * 2 * H];   // [h(96) | g_s(96)] per node, 19.2 MB
__device__ __half g_gd[(size_t)N_NODES * H];       // g_d per node, 9.6 MB
__device__ float  g_WcT[IN_DIM * F];               // combined weight, transposed [256,288]
__device__ float  g_bc[F];
__device__ float  g_zacc[2 * N_NODES];

// ---------------------------------------------------------------------------
// Kernel 1: build combined weight WcT[k][r] and bias bc[r]; zero zacc.
//   rows 0..95   : W_in                      bias b_in
//   rows 96..191 : W_gd @ W_in               bias W_gd @ b_in
//   rows 192..287: W_gs @ W_in               bias W_gs @ b_in + b_gate
// ---------------------------------------------------------------------------
__global__ void prep_kernel(const float* __restrict__ W_in, const float* __restrict__ b_in,
                            const float* __restrict__ W_gate, const float* __restrict__ b_gate) {
    int r = blockIdx.x;      // 0..287
    int k = threadIdx.x;     // 0..255
    float v;
    if (r < H) {
        v = W_in[r * IN_DIM + k];
    } else if (r < 2 * H) {
        int i = r - H;
        float acc = 0.f;
        #pragma unroll 4
        for (int j = 0; j < H; ++j) acc = fmaf(W_gate[i * (2 * H) + j], W_in[j * IN_DIM + k], acc);
        v = acc;
    } else {
        int i = r - 2 * H;
        float acc = 0.f;
        #pragma unroll 4
        for (int j = 0; j < H; ++j) acc = fmaf(W_gate[i * (2 * H) + H + j], W_in[j * IN_DIM + k], acc);
        v = acc;
    }
    g_WcT[k * F + r] = v;

    if (k == 0) {
        float b;
        if (r < H) {
            b = b_in[r];
        } else if (r < 2 * H) {
            int i = r - H;
            float acc = 0.f;
            for (int j = 0; j < H; ++j) acc = fmaf(W_gate[i * (2 * H) + j], b_in[j], acc);
            b = acc;
        } else {
            int i = r - 2 * H;
            float acc = 0.f;
            for (int j = 0; j < H; ++j) acc = fmaf(W_gate[i * (2 * H) + H + j], b_in[j], acc);
            b = acc + b_gate[i];
        }
        g_bc[r] = b;
    }

    for (int idx = blockIdx.x * blockDim.x + threadIdx.x; idx < 2 * N_NODES;
         idx += gridDim.x * blockDim.x)
        g_zacc[idx] = 0.f;
}

// ---------------------------------------------------------------------------
// Kernel 2: feat = x @ WcT + bc  via mma.sync tf32, cp.async double-buffered.
//   Block tile 128x96xK32, 8 warps (4x2), warp tile 32x48, mma m16n8k8.
//   Epilogue converts to fp16 into g_hs / g_gd.
// ---------------------------------------------------------------------------
#define BM 128
#define BN 96
#define BK 32
#define AS_LD 36    // bank = (4*row + k) % 32 -> conflict-free frag loads
#define BS_LD 104   // bank = (8*k + n) % 32  -> conflict-free frag loads
#define KTILES (IN_DIM / BK)   // 8

__device__ __forceinline__ unsigned f2tf32(float f) {
    unsigned u;
    asm("cvt.rna.tf32.f32 %0, %1;" : "=r"(u) : "f"(f));
    return u;
}
__device__ __forceinline__ unsigned smem_u32(const void* p) {
    return (unsigned)__cvta_generic_to_shared(p);
}
__device__ __forceinline__ void cp_async16(unsigned dst, const void* src, bool valid) {
    int sz = valid ? 16 : 0;
    asm volatile("cp.async.cg.shared.global [%0], [%1], 16, %2;\n"
                 :: "r"(dst), "l"(src), "r"(sz));
}

__global__ __launch_bounds__(256) void gemm_tc_kernel(const float* __restrict__ x) {
    __shared__ float As[2][BM][AS_LD];
    __shared__ float Bs[2][BK][BS_LD];

    const int tid  = threadIdx.x;
    const int warp = tid >> 5;
    const int lane = tid & 31;
    const int gid  = lane >> 2;   // 0..7
    const int tig  = lane & 3;    // 0..3

    const int row0 = blockIdx.x * BM;
    const int col0 = blockIdx.y * BN;
    const int wm = warp >> 1;           // 0..3
    const int wn = warp & 1;            // 0..1
    const int m_warp = wm * 32;
    const int n_warp = wn * 48;

    float c[2][6][4];
    #pragma unroll
    for (int i = 0; i < 2; ++i)
        #pragma unroll
        for (int j = 0; j < 6; ++j)
            #pragma unroll
            for (int q = 0; q < 4; ++q) c[i][j][q] = 0.f;

    const int ar = tid >> 3;            // 0..31
    const int ac = (tid & 7) * 4;       // 0..28
    const int bk = tid >> 3;            // 0..31
    const int bc = (tid & 7) * 12;      // 0..84

    // issue loads for tile `t` into buffer `buf`
    auto issue_tile = [&](int buf, int t) {
        int k0 = t * BK;
        #pragma unroll
        for (int p = 0; p < 4; ++p) {
            int r = ar + p * 32;
            int grow = row0 + r;
            bool valid = (grow < N_NODES);
            const float* srcp = x + (size_t)(valid ? grow : 0) * IN_DIM + k0 + ac;
            cp_async16(smem_u32(&As[buf][r][ac]), srcp, valid);
        }
        const float* bp = g_WcT + (size_t)(k0 + bk) * F + col0 + bc;
        #pragma unroll
        for (int q = 0; q < 3; ++q)
            cp_async16(smem_u32(&Bs[buf][bk][bc + q * 4]), bp + q * 4, true);
        asm volatile("cp.async.commit_group;\n");
    };

    issue_tile(0, 0);

    for (int t = 0; t < KTILES; ++t) {
        int cur = t & 1;
        if (t + 1 < KTILES) {
            issue_tile(cur ^ 1, t + 1);
            asm volatile("cp.async.wait_group 1;\n");
        } else {
            asm volatile("cp.async.wait_group 0;\n");
        }
        __syncthreads();

        #pragma unroll
        for (int ks = 0; ks < 4; ++ks) {
            const int kk = ks * 8;
            unsigned a[2][4], b[6][2];
            #pragma unroll
            for (int mt = 0; mt < 2; ++mt) {
                int rA = m_warp + mt * 16 + gid;
                a[mt][0] = f2tf32(As[cur][rA    ][kk + tig    ]);
                a[mt][1] = f2tf32(As[cur][rA + 8][kk + tig    ]);
                a[mt][2] = f2tf32(As[cur][rA    ][kk + tig + 4]);
                a[mt][3] = f2tf32(As[cur][rA + 8][kk + tig + 4]);
            }
            #pragma unroll
            for (int nt = 0; nt < 6; ++nt) {
                int cB = n_warp + nt * 8 + gid;
                b[nt][0] = f2tf32(Bs[cur][kk + tig    ][cB]);
                b[nt][1] = f2tf32(Bs[cur][kk + tig + 4][cB]);
            }
            #pragma unroll
            for (int mt = 0; mt < 2; ++mt)
                #pragma unroll
                for (int nt = 0; nt < 6; ++nt) {
                    asm volatile(
                        "mma.sync.aligned.m16n8k8.row.col.f32.tf32.tf32.f32 "
                        "{%0,%1,%2,%3}, {%4,%5,%6,%7}, {%8,%9}, {%0,%1,%2,%3};\n"
                        : "+f"(c[mt][nt][0]), "+f"(c[mt][nt][1]),
                          "+f"(c[mt][nt][2]), "+f"(c[mt][nt][3])
                        : "r"(a[mt][0]), "r"(a[mt][1]), "r"(a[mt][2]), "r"(a[mt][3]),
                          "r"(b[nt][0]), "r"(b[nt][1]));
                }
        }
        __syncthreads();
    }

    // epilogue: add bias, convert fp16, scatter into g_hs / g_gd.
    #pragma unroll
    for (int mt = 0; mt < 2; ++mt) {
        #pragma unroll
        for (int hf = 0; hf < 2; ++hf) {
            int grow = row0 + m_warp + mt * 16 + gid + hf * 8;
            if (grow >= N_NODES) continue;
            #pragma unroll
            for (int nt = 0; nt < 6; ++nt) {
                int gc = col0 + n_warp + nt * 8 + 2 * tig;    // global column, even
                float v0 = c[mt][nt][hf * 2 + 0] + g_bc[gc];
                float v1 = c[mt][nt][hf * 2 + 1] + g_bc[gc + 1];
                __half2 hv = __floats2half2_rn(v0, v1);
                if (gc < H)           // h
                    *reinterpret_cast<__half2*>(&g_hs[(size_t)grow * 2 * H + gc]) = hv;
                else if (gc < 2 * H)  // g_d
                    *reinterpret_cast<__half2*>(&g_gd[(size_t)grow * H + (gc - H)]) = hv;
                else                  // g_s
                    *reinterpret_cast<__half2*>(&g_hs[(size_t)grow * 2 * H + H + (gc - 2 * H)]) = hv;
            }
        }
    }
}

// ---------------------------------------------------------------------------
// Kernel 3: per-edge. One warp per edge, 3 elements/lane, fp16 gathers.
// ---------------------------------------------------------------------------
__device__ __forceinline__ float fast_tanh(float v) {
    float r;
    asm("tanh.approx.f32 %0, %1;" : "=f"(r) : "f"(v));
    return r;
}
__device__ __forceinline__ void st_cs(float* p, float v) {
    asm volatile("st.global.cs.f32 [%0], %1;" :: "l"(p), "f"(v));
}

__global__ __launch_bounds__(256) void edge_kernel(const int* __restrict__ src,
                                                   const int* __restrict__ dst,
                                                   const float* __restrict__ dvec,
                                                   const float* __restrict__ Wclf,
                                                   float* __restrict__ a_out) {
    const float inv = rsqrtf(2.0f * H);   // 1/sqrt(192)
    int lane = threadIdx.x & 31;
    int warp = (blockIdx.x * blockDim.x + threadIdx.x) >> 5;
    int nwarps = (gridDim.x * blockDim.x) >> 5;

    float c0[3], c1[3];
    #pragma unroll
    for (int k = 0; k < 3; ++k) {
        c0[k] = Wclf[k * 32 + lane];
        c1[k] = Wclf[H + k * 32 + lane];
    }

    for (int e = warp; e < N_EDGES; e += nwarps) {
        int s = __ldg(src + e), t = __ldg(dst + e);
        float ed = __ldg(dvec + s) * __ldg(dvec + t);
        const __half* fs = g_hs + (size_t)s * 2 * H;
        const __half* gd = g_gd + (size_t)t * H;
        float* ao = a_out + (size_t)e * H;
        float s0 = 0.f, s1 = 0.f;
        #pragma unroll
        for (int k = 0; k < 3; ++k) {
            int idx = k * 32 + lane;
            float gdv = __half2float(__ldg(gd + idx));
            float gsv = __half2float(__ldg(fs + H + idx));
            float hv  = __half2float(__ldg(fs + idx));
            float aa = fast_tanh((gdv + gsv) * inv);
            st_cs(ao + idx, aa);
            float m = hv * aa * ed;
            s0 = fmaf(c0[k], m, s0);
            s1 = fmaf(c1[k], m, s1);
        }
        #pragma unroll
        for (int off = 16; off > 0; off >>= 1) {
            s0 += __shfl_down_sync(0xffffffffu, s0, off);
            s1 += __shfl_down_sync(0xffffffffu, s1, off);
        }
        if (lane == 0) {
            atomicAdd(&g_zacc[2 * t + 0], s0);
            atomicAdd(&g_zacc[2 * t + 1], s1);
        }
    }
}

// ---------------------------------------------------------------------------
// Kernel 4: z = log_softmax(zacc + b_clf) over the 2 classes.
// ---------------------------------------------------------------------------
__global__ void final_kernel(const float* __restrict__ b_clf, float* __restrict__ z_out) {
    int n = blockIdx.x * blockDim.x + threadIdx.x;
    if (n >= N_NODES) return;
    float l0 = g_zacc[2 * n + 0] + b_clf[0];
    float l1 = g_zacc[2 * n + 1] + b_clf[1];
    float m = fmaxf(l0, l1);
    float lse = m + logf(expf(l0 - m) + expf(l1 - m));
    z_out[2 * n + 0] = l0 - lse;
    z_out[2 * n + 1] = l1 - lse;
}

// ---------------------------------------------------------------------------
extern "C" void kernel_launch(void* const* d_in, const int* in_sizes, int n_in,
                              void* d_out, int out_size) {
    const float* x      = (const float*)d_in[0];
    const float* dvec   = (const float*)d_in[1];
    const int*   src    = (const int*)  d_in[2];
    const int*   dst    = (const int*)  d_in[3];
    const float* W_in   = (const float*)d_in[4];
    const float* b_in   = (const float*)d_in[5];
    const float* W_gate = (const float*)d_in[6];
    const float* b_gate = (const float*)d_in[7];
    const float* W_clf  = (const float*)d_in[8];
    const float* b_clf  = (const float*)d_in[9];

    float* out   = (float*)d_out;
    float* z_out = out;                 // [N, 2]
    float* a_out = out + 2 * N_NODES;   // [E, 96]

    prep_kernel<<<F, 256>>>(W_in, b_in, W_gate, b_gate);

    dim3 ggrid((N_NODES + BM - 1) / BM, F / BN);
    gemm_tc_kernel<<<ggrid, 256>>>(x);

    edge_kernel<<<4096, 256>>>(src, dst, dvec, W_clf, a_out);

    final_kernel<<<(N_NODES + 255) / 256, 256>>>(b_clf, z_out);
}

// round 4
// speedup vs baseline: 2.3785x; 1.0373x over previous
#include <cuda_runtime.h>
#include <cuda_fp16.h>
#include <math.h>

#define N_NODES 50000
#define N_EDGES 800000
#define H       96
#define IN_DIM  256
#define F       288   // combined output: [ h(96) | g_d(96) | g_s(96) ]

// Scratch (device globals — no allocation in kernel_launch)
__device__ __half g_hs[(size_t)N_NODES * 2 * H];   // [h(96) | g_s(96)] per node
__device__ __half g_gd[(size_t)N_NODES * H];       // g_d per node
__device__ float  g_WcT[IN_DIM * F];               // combined weight, tf32-rounded bits
__device__ float  g_bc[F];
__device__ float  g_zacc[2 * N_NODES];

__device__ __forceinline__ unsigned f2tf32(float f) {
    unsigned u;
    asm("cvt.rna.tf32.f32 %0, %1;" : "=r"(u) : "f"(f));
    return u;
}

// ---------------------------------------------------------------------------
// Kernel 1: build combined weight WcT[k][r] (pre-rounded to tf32) and bias;
// zero zacc.
// ---------------------------------------------------------------------------
__global__ void prep_kernel(const float* __restrict__ W_in, const float* __restrict__ b_in,
                            const float* __restrict__ W_gate, const float* __restrict__ b_gate) {
    int r = blockIdx.x;      // 0..287
    int k = threadIdx.x;     // 0..255
    float v;
    if (r < H) {
        v = W_in[r * IN_DIM + k];
    } else if (r < 2 * H) {
        int i = r - H;
        float acc = 0.f;
        #pragma unroll 4
        for (int j = 0; j < H; ++j) acc = fmaf(W_gate[i * (2 * H) + j], W_in[j * IN_DIM + k], acc);
        v = acc;
    } else {
        int i = r - 2 * H;
        float acc = 0.f;
        #pragma unroll 4
        for (int j = 0; j < H; ++j) acc = fmaf(W_gate[i * (2 * H) + H + j], W_in[j * IN_DIM + k], acc);
        v = acc;
    }
    g_WcT[k * F + r] = __uint_as_float(f2tf32(v));   // pre-rounded for mma

    if (k == 0) {
        float b;
        if (r < H) {
            b = b_in[r];
        } else if (r < 2 * H) {
            int i = r - H;
            float acc = 0.f;
            for (int j = 0; j < H; ++j) acc = fmaf(W_gate[i * (2 * H) + j], b_in[j], acc);
            b = acc;
        } else {
            int i = r - 2 * H;
            float acc = 0.f;
            for (int j = 0; j < H; ++j) acc = fmaf(W_gate[i * (2 * H) + H + j], b_in[j], acc);
            b = acc + b_gate[i];
        }
        g_bc[r] = b;
    }

    for (int idx = blockIdx.x * blockDim.x + threadIdx.x; idx < 2 * N_NODES;
         idx += gridDim.x * blockDim.x)
        g_zacc[idx] = 0.f;
}

// ---------------------------------------------------------------------------
// Kernel 2: feat = x @ WcT + bc  via mma.sync tf32, cp.async double-buffered.
//   Block tile 128x96xK32, 8 warps (4x2), warp tile 32x48, mma m16n8k8.
//   B is pre-rounded tf32 (no cvt in inner loop). Epilogue -> fp16 features.
// ---------------------------------------------------------------------------
#define BM 128
#define BN 96
#define BK 32
#define AS_LD 36    // bank = (4*row + k) % 32 -> conflict-free frag loads
#define BS_LD 104   // bank = (8*k + n) % 32  -> conflict-free frag loads
#define KTILES (IN_DIM / BK)   // 8

__device__ __forceinline__ unsigned smem_u32(const void* p) {
    return (unsigned)__cvta_generic_to_shared(p);
}
__device__ __forceinline__ void cp_async16(unsigned dst, const void* src, bool valid) {
    int sz = valid ? 16 : 0;
    asm volatile("cp.async.cg.shared.global [%0], [%1], 16, %2;\n"
                 :: "r"(dst), "l"(src), "r"(sz));
}

__global__ __launch_bounds__(256) void gemm_tc_kernel(const float* __restrict__ x) {
    __shared__ float As[2][BM][AS_LD];
    __shared__ float Bs[2][BK][BS_LD];

    const int tid  = threadIdx.x;
    const int warp = tid >> 5;
    const int lane = tid & 31;
    const int gid  = lane >> 2;   // 0..7
    const int tig  = lane & 3;    // 0..3

    const int row0 = blockIdx.x * BM;
    const int col0 = blockIdx.y * BN;
    const int wm = warp >> 1;           // 0..3
    const int wn = warp & 1;            // 0..1
    const int m_warp = wm * 32;
    const int n_warp = wn * 48;

    float c[2][6][4];
    #pragma unroll
    for (int i = 0; i < 2; ++i)
        #pragma unroll
        for (int j = 0; j < 6; ++j)
            #pragma unroll
            for (int q = 0; q < 4; ++q) c[i][j][q] = 0.f;

    const int ar = tid >> 3;            // 0..31
    const int ac = (tid & 7) * 4;       // 0..28
    const int bk = tid >> 3;            // 0..31
    const int bc = (tid & 7) * 12;      // 0..84

    auto issue_tile = [&](int buf, int t) {
        int k0 = t * BK;
        #pragma unroll
        for (int p = 0; p < 4; ++p) {
            int r = ar + p * 32;
            int grow = row0 + r;
            bool valid = (grow < N_NODES);
            const float* srcp = x + (size_t)(valid ? grow : 0) * IN_DIM + k0 + ac;
            cp_async16(smem_u32(&As[buf][r][ac]), srcp, valid);
        }
        const float* bp = g_WcT + (size_t)(k0 + bk) * F + col0 + bc;
        #pragma unroll
        for (int q = 0; q < 3; ++q)
            cp_async16(smem_u32(&Bs[buf][bk][bc + q * 4]), bp + q * 4, true);
        asm volatile("cp.async.commit_group;\n");
    };

    issue_tile(0, 0);

    for (int t = 0; t < KTILES; ++t) {
        int cur = t & 1;
        if (t + 1 < KTILES) {
            issue_tile(cur ^ 1, t + 1);
            asm volatile("cp.async.wait_group 1;\n");
        } else {
            asm volatile("cp.async.wait_group 0;\n");
        }
        __syncthreads();

        #pragma unroll
        for (int ks = 0; ks < 4; ++ks) {
            const int kk = ks * 8;
            unsigned a[2][4], b[6][2];
            #pragma unroll
            for (int mt = 0; mt < 2; ++mt) {
                int rA = m_warp + mt * 16 + gid;
                a[mt][0] = f2tf32(As[cur][rA    ][kk + tig    ]);
                a[mt][1] = f2tf32(As[cur][rA + 8][kk + tig    ]);
                a[mt][2] = f2tf32(As[cur][rA    ][kk + tig + 4]);
                a[mt][3] = f2tf32(As[cur][rA + 8][kk + tig + 4]);
            }
            #pragma unroll
            for (int nt = 0; nt < 6; ++nt) {
                int cB = n_warp + nt * 8 + gid;
                b[nt][0] = __float_as_uint(Bs[cur][kk + tig    ][cB]);   // pre-rounded
                b[nt][1] = __float_as_uint(Bs[cur][kk + tig + 4][cB]);
            }
            #pragma unroll
            for (int mt = 0; mt < 2; ++mt)
                #pragma unroll
                for (int nt = 0; nt < 6; ++nt) {
                    asm volatile(
                        "mma.sync.aligned.m16n8k8.row.col.f32.tf32.tf32.f32 "
                        "{%0,%1,%2,%3}, {%4,%5,%6,%7}, {%8,%9}, {%0,%1,%2,%3};\n"
                        : "+f"(c[mt][nt][0]), "+f"(c[mt][nt][1]),
                          "+f"(c[mt][nt][2]), "+f"(c[mt][nt][3])
                        : "r"(a[mt][0]), "r"(a[mt][1]), "r"(a[mt][2]), "r"(a[mt][3]),
                          "r"(b[nt][0]), "r"(b[nt][1]));
                }
        }
        __syncthreads();
    }

    // epilogue: add bias, convert fp16, scatter into g_hs / g_gd.
    #pragma unroll
    for (int mt = 0; mt < 2; ++mt) {
        #pragma unroll
        for (int hf = 0; hf < 2; ++hf) {
            int grow = row0 + m_warp + mt * 16 + gid + hf * 8;
            if (grow >= N_NODES) continue;
            #pragma unroll
            for (int nt = 0; nt < 6; ++nt) {
                int gc = col0 + n_warp + nt * 8 + 2 * tig;
                float v0 = c[mt][nt][hf * 2 + 0] + g_bc[gc];
                float v1 = c[mt][nt][hf * 2 + 1] + g_bc[gc + 1];
                __half2 hv = __floats2half2_rn(v0, v1);
                if (gc < H)
                    *reinterpret_cast<__half2*>(&g_hs[(size_t)grow * 2 * H + gc]) = hv;
                else if (gc < 2 * H)
                    *reinterpret_cast<__half2*>(&g_gd[(size_t)grow * H + (gc - H)]) = hv;
                else
                    *reinterpret_cast<__half2*>(&g_hs[(size_t)grow * 2 * H + H + (gc - 2 * H)]) = hv;
            }
        }
    }
}

// ---------------------------------------------------------------------------
// Kernel 3: per-edge. 16 lanes per edge (2 edges per warp), half2 gathers,
//           vectorized streaming stores.
// ---------------------------------------------------------------------------
__device__ __forceinline__ float fast_tanh(float v) {
    float r;
    asm("tanh.approx.f32 %0, %1;" : "=f"(r) : "f"(v));
    return r;
}
__device__ __forceinline__ void st_cs_v2(float* p, float a, float b) {
    asm volatile("st.global.cs.v2.f32 [%0], {%1,%2};" :: "l"(p), "f"(a), "f"(b));
}

__global__ __launch_bounds__(256) void edge_kernel(const int* __restrict__ src,
                                                   const int* __restrict__ dst,
                                                   const float* __restrict__ dvec,
                                                   const float* __restrict__ Wclf,
                                                   float* __restrict__ a_out) {
    const float inv = rsqrtf(2.0f * H);   // 1/sqrt(192)
    const int lane = threadIdx.x & 31;
    const int sub  = lane >> 4;           // which edge of the pair
    const int sl   = lane & 15;           // sublane within edge, owns elems 6sl..6sl+5
    const int warp = (blockIdx.x * blockDim.x + threadIdx.x) >> 5;
    const int nwarps = (gridDim.x * blockDim.x) >> 5;
    const int NPAIRS = N_EDGES / 2;

    float c0[6], c1[6];
    #pragma unroll
    for (int q = 0; q < 6; ++q) {
        c0[q] = Wclf[6 * sl + q];
        c1[q] = Wclf[H + 6 * sl + q];
    }

    for (int p = warp; p < NPAIRS; p += nwarps) {
        int e = 2 * p + sub;
        int s = __ldg(src + e), t = __ldg(dst + e);
        float ed = __ldg(dvec + s) * __ldg(dvec + t);
        const __half2* fh = reinterpret_cast<const __half2*>(g_hs + (size_t)s * 2 * H) + 3 * sl;
        const __half2* fg = reinterpret_cast<const __half2*>(g_hs + (size_t)s * 2 * H + H) + 3 * sl;
        const __half2* fd = reinterpret_cast<const __half2*>(g_gd + (size_t)t * H) + 3 * sl;

        float s0 = 0.f, s1 = 0.f;
        float av[6];
        #pragma unroll
        for (int q = 0; q < 3; ++q) {
            float2 gd = __half22float2(__ldg(fd + q));
            float2 gs = __half22float2(__ldg(fg + q));
            float2 hh = __half22float2(__ldg(fh + q));
            float a0 = fast_tanh((gd.x + gs.x) * inv);
            float a1 = fast_tanh((gd.y + gs.y) * inv);
            av[2 * q]     = a0;
            av[2 * q + 1] = a1;
            float m0 = hh.x * a0 * ed;
            float m1 = hh.y * a1 * ed;
            s0 = fmaf(c0[2 * q], m0, fmaf(c0[2 * q + 1], m1, s0));
            s1 = fmaf(c1[2 * q], m0, fmaf(c1[2 * q + 1], m1, s1));
        }
        float* aop = a_out + (size_t)e * H + 6 * sl;
        st_cs_v2(aop + 0, av[0], av[1]);
        st_cs_v2(aop + 2, av[2], av[3]);
        st_cs_v2(aop + 4, av[4], av[5]);

        #pragma unroll
        for (int off = 8; off > 0; off >>= 1) {
            s0 += __shfl_down_sync(0xffffffffu, s0, off);
            s1 += __shfl_down_sync(0xffffffffu, s1, off);
        }
        if (sl == 0) {
            atomicAdd(&g_zacc[2 * t + 0], s0);
            atomicAdd(&g_zacc[2 * t + 1], s1);
        }
    }
}

// ---------------------------------------------------------------------------
// Kernel 4: z = log_softmax(zacc + b_clf) over the 2 classes.
// ---------------------------------------------------------------------------
__global__ void final_kernel(const float* __restrict__ b_clf, float* __restrict__ z_out) {
    int n = blockIdx.x * blockDim.x + threadIdx.x;
    if (n >= N_NODES) return;
    float l0 = g_zacc[2 * n + 0] + b_clf[0];
    float l1 = g_zacc[2 * n + 1] + b_clf[1];
    float m = fmaxf(l0, l1);
    float lse = m + logf(expf(l0 - m) + expf(l1 - m));
    z_out[2 * n + 0] = l0 - lse;
    z_out[2 * n + 1] = l1 - lse;
}

// ---------------------------------------------------------------------------
extern "C" void kernel_launch(void* const* d_in, const int* in_sizes, int n_in,
                              void* d_out, int out_size) {
    const float* x      = (const float*)d_in[0];
    const float* dvec   = (const float*)d_in[1];
    const int*   src    = (const int*)  d_in[2];
    const int*   dst    = (const int*)  d_in[3];
    const float* W_in   = (const float*)d_in[4];
    const float* b_in   = (const float*)d_in[5];
    const float* W_gate = (const float*)d_in[6];
    const float* b_gate = (const float*)d_in[7];
    const float* W_clf  = (const float*)d_in[8];
    const float* b_clf  = (const float*)d_in[9];

    float* out   = (float*)d_out;
    float* z_out = out;                 // [N, 2]
    float* a_out = out + 2 * N_NODES;   // [E, 96]

    prep_kernel<<<F, 256>>>(W_in, b_in, W_gate, b_gate);

    dim3 ggrid((N_NODES + BM - 1) / BM, F / BN);
    gemm_tc_kernel<<<ggrid, 256>>>(x);

    edge_kernel<<<2048, 256>>>(src, dst, dvec, W_clf, a_out);

    final_kernel<<<(N_NODES + 255) / 256, 256>>>(b_clf, z_out);
}